// round 12
// baseline (speedup 1.0000x reference)
#include <cuda_runtime.h>

// Problem constants (fixed by the reference: N=16384, D=2, H=128)
constexpr int N_ROWS = 16384;
constexpr int H      = 128;
constexpr int NHi    = N_ROWS * H;          // floats per [N,H] tensor

constexpr int THREADS = 256;
constexpr int WPB     = 8;                           // warps per block

// K1: streaming pass (reads enc+dec, writes bi_enc#1 + bi_dec = 50.3 MB)
constexpr int BLOCKS1 = 1024;
constexpr int TW1     = BLOCKS1 * WPB;               // 8192 warps
constexpr int RPW1    = N_ROWS / TW1;                // 2 rows/warp

// K2: copy bi_enc#1 -> bi_enc#2 (L2-hot) + exact nce (dot is free on the way)
constexpr int BLOCKS2 = 512;
constexpr int RPW2    = 4;                           // rows per warp

// Persistent scratch (allocation-free __device__ globals). g_h is fully
// overwritten each run; the rest re-zeroed by K2's elected last block.
__device__ float    g_h[N_ROWS];       // per-row: -N*||e||^2 + 10*diag
__device__ float    g_ysum[H];         // sum_y bi_dec[y][c]
__device__ float    g_scalars[3];      // [0]=Synorm  [1]=sum diag  [2]=nce
__device__ unsigned g_ticket;          // last-block election (K2)

__device__ __forceinline__ float warp_sum(float v) {
    #pragma unroll
    for (int o = 16; o > 0; o >>= 1) v += __shfl_down_sync(0xffffffffu, v, o);
    return v;
}

// ---------------------------------------------------------------------------
// K1: stream enc+dec once (33.5 MB in, 16.8 MB out). The bi_enc duplicate
// store is deliberately NOT done here — K2 does it from L2.
// ---------------------------------------------------------------------------
__global__ __launch_bounds__(THREADS) void stream_kernel(
    const float* __restrict__ enc, const float* __restrict__ dec,
    float* __restrict__ out)
{
    const int tid   = threadIdx.x;
    const int lane  = tid & 31;
    const int w     = tid >> 5;
    const int gwarp = blockIdx.x * WPB + w;

    float ys0 = 0.f, ys1 = 0.f, ys2 = 0.f, ys3 = 0.f;
    float ynorm = 0.f, dgsum = 0.f;
    float hp[RPW1];

    #pragma unroll
    for (int i = 0; i < RPW1; i++) {
        const int r = gwarp + i * TW1;
        // row r = 256 floats = 64 float4; direction halves at +0 / +32
        const float4 a = __ldg((const float4*)enc + r * 64 + lane);
        const float4 b = __ldg((const float4*)enc + r * 64 + 32 + lane);
        const float4 c = __ldg((const float4*)dec + r * 64 + lane);
        const float4 d = __ldg((const float4*)dec + r * 64 + 32 + lane);

        float4 e; e.x = a.x + b.x; e.y = a.y + b.y; e.z = a.z + b.z; e.w = a.w + b.w;
        float4 f; f.x = c.x + d.x; f.y = c.y + d.y; f.z = c.z + d.z; f.w = c.w + d.w;

        ((float4*)out)[r * 32 + lane] = e;                   // bi_enc #1 (keep in L2)
        __stcs((float4*)out + NHi / 2 + r * 32 + lane, f);   // bi_dec (evict-first)

        ys0 += f.x; ys1 += f.y; ys2 += f.z; ys3 += f.w;
        ynorm += f.x * f.x + f.y * f.y + f.z * f.z + f.w * f.w;

        const float en  = e.x * e.x + e.y * e.y + e.z * e.z + e.w * e.w;
        const float gx = e.x - f.x, gy = e.y - f.y, gz = e.z - f.z, gw = e.w - f.w;
        const float dgl = gx * gx + gy * gy + gz * gz + gw * gw;

        dgsum += dgl;
        hp[i] = fmaf(-(float)N_ROWS, en, 10.0f * dgl);
    }

    // Deferred reductions: 4 independent shfl chains, interleaved by ptxas.
    float h0 = hp[0], h1 = hp[1];
    #pragma unroll
    for (int o = 16; o > 0; o >>= 1) {
        h0    += __shfl_down_sync(0xffffffffu, h0, o);
        h1    += __shfl_down_sync(0xffffffffu, h1, o);
        ynorm += __shfl_down_sync(0xffffffffu, ynorm, o);
        dgsum += __shfl_down_sync(0xffffffffu, dgsum, o);
    }
    if (lane == 0) {
        g_h[gwarp]       = h0;
        g_h[gwarp + TW1] = h1;
    }

    __shared__ float s_ys[WPB][H];
    __shared__ float s_sc[WPB][2];
    s_ys[w][4 * lane + 0] = ys0;
    s_ys[w][4 * lane + 1] = ys1;
    s_ys[w][4 * lane + 2] = ys2;
    s_ys[w][4 * lane + 3] = ys3;
    if (lane == 0) { s_sc[w][0] = ynorm; s_sc[w][1] = dgsum; }
    __syncthreads();

    if (tid < H) {
        float s = 0.f;
        #pragma unroll
        for (int ww = 0; ww < WPB; ww++) s += s_ys[ww][tid];
        atomicAdd(&g_ysum[tid], s);
    } else if (tid == H) {
        float yn = 0.f, ds = 0.f;
        #pragma unroll
        for (int ww = 0; ww < WPB; ww++) { yn += s_sc[ww][0]; ds += s_sc[ww][1]; }
        atomicAdd(&g_scalars[0], yn);
        atomicAdd(&g_scalars[1], ds);
    }
}

// ---------------------------------------------------------------------------
// K2: read bi_enc#1 (L2-hot), write bi_enc#2, and compute EXACT nce — the
// e-rows are in registers for the copy, so the dot with Ysum is free.
// 4 contiguous rows/warp, all loads front-issued, 4 interleaved butterflies.
// Last block (ticket) writes the scalars and re-zeros persistent state.
// ---------------------------------------------------------------------------
__global__ __launch_bounds__(THREADS) void nce_copy_kernel(float* __restrict__ out)
{
    const int tid   = threadIdx.x;
    const int lane  = tid & 31;
    const int w     = tid >> 5;
    const int rbase = (blockIdx.x * WPB + w) * RPW2;     // 4 contiguous rows

    // ---- front-issue every load ----
    const float4 e0 = __ldg((const float4*)out + (rbase + 0) * 32 + lane);
    const float4 e1 = __ldg((const float4*)out + (rbase + 1) * 32 + lane);
    const float4 e2 = __ldg((const float4*)out + (rbase + 2) * 32 + lane);
    const float4 e3 = __ldg((const float4*)out + (rbase + 3) * 32 + lane);
    const float  hv = __ldg(&g_h[rbase + (lane & 3)]);   // lane l holds h[row l&3]
    const float4 ys = ((const float4*)g_ysum)[lane];
    const float  syn = g_scalars[0];

    // ---- the duplicate store (bi_enc#2), evict-first ----
    __stcs((float4*)out + NHi / 4 + (rbase + 0) * 32 + lane, e0);
    __stcs((float4*)out + NHi / 4 + (rbase + 1) * 32 + lane, e1);
    __stcs((float4*)out + NHi / 4 + (rbase + 2) * 32 + lane, e2);
    __stcs((float4*)out + NHi / 4 + (rbase + 3) * 32 + lane, e3);

    // ---- exact per-row dot with Ysum ----
    float dp0 = e0.x * ys.x + e0.y * ys.y + e0.z * ys.z + e0.w * ys.w;
    float dp1 = e1.x * ys.x + e1.y * ys.y + e1.z * ys.z + e1.w * ys.w;
    float dp2 = e2.x * ys.x + e2.y * ys.y + e2.z * ys.z + e2.w * ys.w;
    float dp3 = e3.x * ys.x + e3.y * ys.y + e3.z * ys.z + e3.w * ys.w;

    #pragma unroll
    for (int o = 16; o > 0; o >>= 1) {
        dp0 += __shfl_xor_sync(0xffffffffu, dp0, o);
        dp1 += __shfl_xor_sync(0xffffffffu, dp1, o);
        dp2 += __shfl_xor_sync(0xffffffffu, dp2, o);
        dp3 += __shfl_xor_sync(0xffffffffu, dp3, o);
    }

    // lanes 0..3 finalize their row in parallel (h already lane-local)
    float dsel = dp0;
    if (lane == 1) dsel = dp1;
    else if (lane == 2) dsel = dp2;
    else if (lane == 3) dsel = dp3;

    float acc = 0.f;
    if (lane < 4)
        acc = fmaxf(5.0f - syn + fmaf(2.0f, dsel, hv), 0.0f);
    acc += __shfl_xor_sync(0xffffffffu, acc, 1);
    acc += __shfl_xor_sync(0xffffffffu, acc, 2);     // lane 0: warp total

    __shared__ float s_nce[WPB];
    if (lane == 0) s_nce[w] = acc;
    __syncthreads();

    if (tid == 0) {
        float tn = 0.f;
        #pragma unroll
        for (int ww = 0; ww < WPB; ww++) tn += s_nce[ww];
        atomicAdd(&g_scalars[2], tn);
        __threadfence();
        // Last-arriving block writes outputs and re-zeros persistent state.
        if (atomicAdd(&g_ticket, 1u) == BLOCKS2 - 1) {
            const float nce  = atomicAdd(&g_scalars[2], 0.0f);
            const float diag = g_scalars[1];
            out[3 * NHi]     = nce;                        // nce_loss
            out[3 * NHi + 1] = -diag / (float)N_ROWS;      // diagonal_loss
            #pragma unroll
            for (int i = 0; i < H; i++) g_ysum[i] = 0.0f;
            g_scalars[0] = 0.0f; g_scalars[1] = 0.0f; g_scalars[2] = 0.0f;
            atomicExch(&g_ticket, 0u);
        }
    }
}

extern "C" void kernel_launch(void* const* d_in, const int* in_sizes, int n_in,
                              void* d_out, int out_size) {
    const float* enc = (const float*)d_in[0];
    const float* dec = (const float*)d_in[1];
    float* out = (float*)d_out;

    stream_kernel<<<BLOCKS1, THREADS>>>(enc, dec, out);
    nce_copy_kernel<<<BLOCKS2, THREADS>>>(out);
}

// round 13
// speedup vs baseline: 1.1364x; 1.1364x over previous
#include <cuda_runtime.h>

// Problem constants (fixed by the reference: N=16384, D=2, H=128)
constexpr int N_ROWS = 16384;
constexpr int H      = 128;
constexpr int NHi    = N_ROWS * H;          // floats per [N,H] tensor

constexpr int THREADS = 256;
constexpr int WPB     = 8;                           // warps per block
constexpr int SBLOCKS = 1024;                        // streaming blocks
constexpr int TW      = SBLOCKS * WPB;               // 8192 warps
constexpr int RPW     = N_ROWS / TW;                 // 2 rows/warp
constexpr int GRID    = SBLOCKS + 1;                 // + 1 waiter block

// Persistent scratch (allocation-free __device__ globals). Zero at module
// load; the waiter block re-zeros everything at the end of every run.
__device__ float    g_h[N_ROWS];     // per-row: -N*||e||^2 + 10*diag
__device__ float    g_ysum[H];       // sum_y bi_dec[y][c]
__device__ float    g_scalars[2];    // [0]=Synorm  [1]=sum diag
__device__ unsigned g_maxh;          // monotone-mapped max over rows of h
__device__ unsigned g_maxxn;         // monotone-mapped max over rows of xnorm
__device__ unsigned g_done;          // streaming blocks completed

// Monotone float<->uint mapping (order-preserving for ALL floats).
__device__ __forceinline__ unsigned fmap(float f) {
    unsigned u = __float_as_uint(f);
    return (u & 0x80000000u) ? ~u : (u | 0x80000000u);
}
__device__ __forceinline__ float funmap(unsigned m) {
    return (m & 0x80000000u) ? __uint_as_float(m ^ 0x80000000u)
                             : __uint_as_float(~m);
}

__device__ __forceinline__ float warp_sum(float v) {
    #pragma unroll
    for (int o = 16; o > 0; o >>= 1) v += __shfl_down_sync(0xffffffffu, v, o);
    return v;
}

__global__ __launch_bounds__(THREADS) void fused_kernel(
    const float* __restrict__ enc, const float* __restrict__ dec,
    float* __restrict__ out)
{
    const int tid  = threadIdx.x;
    const int lane = tid & 31;
    const int w    = tid >> 5;

    // =====================  WAITER BLOCK  =====================
    if (blockIdx.x == SBLOCKS) {
        __shared__ float s_ysm[H];
        __shared__ float s_red[WPB];
        __shared__ float s_env[4];   // [0]=ysn2 [1]=syn [2]=cert_ub [3]=nce

        if (tid == 0) {
            while (__ldcg(&g_done) != (unsigned)SBLOCKS) __nanosleep(128);
        }
        __syncthreads();
        __threadfence();   // acquire: streamers' fenced writes now visible

        // ||Ysum||^2 (+ stash Ysum in shared for the dormant fallback)
        float v = (tid < H) ? __ldcg(&g_ysum[tid]) : 0.0f;
        if (tid < H) s_ysm[tid] = v;
        float ysq = warp_sum(v * v);
        if (lane == 0) s_red[w] = ysq;
        __syncthreads();
        if (tid == 0) {
            float ysn2 = 0.f;
            #pragma unroll
            for (int ww = 0; ww < WPB; ww++) ysn2 += s_red[ww];
            const float syn  = __ldcg(&g_scalars[0]);
            const float mxh  = funmap(g_maxh);
            const float mxxn = funmap(g_maxxn);
            // Global certificate: for every row x,
            //   row_loss <= 5 - syn + maxH + 2*sqrt(maxXnorm*||Ysum||^2)
            const float ub = 5.0f - syn + mxh + 2.0f * sqrtf(mxxn * ysn2)
                           + 16.0f + 1e-5f * (fabsf(mxh) + fabsf(syn));
            s_env[0] = ysn2; s_env[1] = syn; s_env[2] = ub;
        }
        __syncthreads();

        float nce = 0.0f;
        if (s_env[2] > 0.0f) {
            // Exact fallback (dormant on this data; correct in general):
            // one warp per row, strided, dot bi_enc row with shared Ysum.
            const float syn = s_env[1];
            const int gw = w;                         // warp 0..7
            float acc = 0.f;
            for (int r = gw; r < N_ROWS; r += WPB) {
                const float4 e  = __ldcg((const float4*)out + r * 32 + lane);
                const float4 yv = ((const float4*)s_ysm)[lane];
                float dp = e.x * yv.x + e.y * yv.y + e.z * yv.z + e.w * yv.w;
                dp = warp_sum(dp);
                if (lane == 0)
                    acc += fmaxf(5.0f - syn + fmaf(2.0f, dp, __ldcg(&g_h[r])), 0.0f);
            }
            if (lane == 0) s_red[w] = acc;
            __syncthreads();
            if (tid == 0) {
                float t = 0.f;
                #pragma unroll
                for (int ww = 0; ww < WPB; ww++) t += s_red[ww];
                s_env[3] = t;
            }
            __syncthreads();
            nce = s_env[3];
        }

        if (tid == 0) {
            out[3 * NHi]     = nce;                                    // nce_loss
            out[3 * NHi + 1] = -__ldcg(&g_scalars[1]) / (float)N_ROWS; // diagonal_loss
        }
        // Re-zero persistent state for the next graph replay.
        if (tid < H) g_ysum[tid] = 0.0f;
        if (tid == H)     g_scalars[0] = 0.0f;
        if (tid == H + 1) g_scalars[1] = 0.0f;
        if (tid == H + 2) { g_maxh = 0u; g_maxxn = 0u; }
        __syncthreads();
        if (tid == 0) atomicExch(&g_done, 0u);
        return;
    }

    // =====================  STREAMING BLOCKS  =====================
    const int gwarp = blockIdx.x * WPB + w;

    float ys0 = 0.f, ys1 = 0.f, ys2 = 0.f, ys3 = 0.f;
    float ynorm = 0.f, dgsum = 0.f;
    float hp[RPW], xp[RPW];

    #pragma unroll
    for (int i = 0; i < RPW; i++) {
        const int r = gwarp + i * TW;
        // row r = 256 floats = 64 float4; direction halves at +0 / +32
        const float4 a = __ldg((const float4*)enc + r * 64 + lane);
        const float4 b = __ldg((const float4*)enc + r * 64 + 32 + lane);
        const float4 c = __ldg((const float4*)dec + r * 64 + lane);
        const float4 d = __ldg((const float4*)dec + r * 64 + 32 + lane);

        float4 e; e.x = a.x + b.x; e.y = a.y + b.y; e.z = a.z + b.z; e.w = a.w + b.w;
        float4 f; f.x = c.x + d.x; f.y = c.y + d.y; f.z = c.z + d.z; f.w = c.w + d.w;

        ((float4*)out)[r * 32 + lane] = e;                   // bi_enc #1
        __stcs((float4*)out + NHi / 4 + r * 32 + lane, e);   // bi_enc copy
        __stcs((float4*)out + NHi / 2 + r * 32 + lane, f);   // bi_dec

        ys0 += f.x; ys1 += f.y; ys2 += f.z; ys3 += f.w;
        ynorm += f.x * f.x + f.y * f.y + f.z * f.z + f.w * f.w;

        const float en  = e.x * e.x + e.y * e.y + e.z * e.z + e.w * e.w;
        const float gx = e.x - f.x, gy = e.y - f.y, gz = e.z - f.z, gw = e.w - f.w;
        const float dgl = gx * gx + gy * gy + gz * gz + gw * gw;

        dgsum += dgl;
        xp[i] = en;
        hp[i] = fmaf(-(float)N_ROWS, en, 10.0f * dgl);
    }

    // Deferred reductions: 6 independent shfl chains, interleaved by ptxas.
    float h0 = hp[0], h1 = hp[1], x0 = xp[0], x1 = xp[1];
    #pragma unroll
    for (int o = 16; o > 0; o >>= 1) {
        h0    += __shfl_down_sync(0xffffffffu, h0, o);
        h1    += __shfl_down_sync(0xffffffffu, h1, o);
        x0    += __shfl_down_sync(0xffffffffu, x0, o);
        x1    += __shfl_down_sync(0xffffffffu, x1, o);
        ynorm += __shfl_down_sync(0xffffffffu, ynorm, o);
        dgsum += __shfl_down_sync(0xffffffffu, dgsum, o);
    }

    __shared__ float s_ys[WPB][H];
    __shared__ float s_sc[WPB][4];
    if (lane == 0) {
        g_h[gwarp]      = h0;
        g_h[gwarp + TW] = h1;
        s_sc[w][0] = ynorm; s_sc[w][1] = dgsum;
        s_sc[w][2] = fmaxf(h0, h1); s_sc[w][3] = fmaxf(x0, x1);
    }
    s_ys[w][4 * lane + 0] = ys0;
    s_ys[w][4 * lane + 1] = ys1;
    s_ys[w][4 * lane + 2] = ys2;
    s_ys[w][4 * lane + 3] = ys3;
    __syncthreads();

    if (tid < H) {
        float s = 0.f;
        #pragma unroll
        for (int ww = 0; ww < WPB; ww++) s += s_ys[ww][tid];
        atomicAdd(&g_ysum[tid], s);
    } else if (tid == H) {
        float yn = 0.f, ds = 0.f;
        #pragma unroll
        for (int ww = 0; ww < WPB; ww++) { yn += s_sc[ww][0]; ds += s_sc[ww][1]; }
        atomicAdd(&g_scalars[0], yn);
        atomicAdd(&g_scalars[1], ds);
    } else if (tid == H + 1) {
        float mh = s_sc[0][2], mx = s_sc[0][3];
        #pragma unroll
        for (int ww = 1; ww < WPB; ww++) {
            mh = fmaxf(mh, s_sc[ww][2]); mx = fmaxf(mx, s_sc[ww][3]);
        }
        atomicMax(&g_maxh,  fmap(mh));
        atomicMax(&g_maxxn, fmap(mx));
    }

    // Publish everything (g_h stores + atomics), then signal completion.
    __threadfence();
    __syncthreads();
    if (tid == 0) atomicAdd(&g_done, 1u);
}

extern "C" void kernel_launch(void* const* d_in, const int* in_sizes, int n_in,
                              void* d_out, int out_size) {
    const float* enc = (const float*)d_in[0];
    const float* dec = (const float*)d_in[1];
    float* out = (float*)d_out;

    fused_kernel<<<GRID, THREADS>>>(enc, dec, out);
}